// round 1
// baseline (speedup 1.0000x reference)
#include <cuda_runtime.h>

// Problem dims
#define NB 16
#define NS 2048
#define ND 64
#define NO 128

// Kernel-1 split-K
#define SPLIT 16
#define KCH (NS / SPLIT)   // 128
#define KT 32

// Kernel-2 smem row padding (floats). 68 keeps float4 alignment and breaks
// the row-size==multiple-of-32-banks conflict.
#define PAD 68

// Scratch (allocation-free rule: __device__ globals)
__device__ float g_Ypart[SPLIT * NB * NO * ND];   // 8 MB
__device__ float g_Y[NB * NO * ND];               // 512 KB

// ---------------------------------------------------------------------------
// Kernel 1: per-batch partial GEMM  Ypart[sp][b][o][d] = sum_{k in chunk} W[o,k] * x[b,k,d]
// grid (NB, SPLIT), 256 threads. Output tile 128(o) x 64(d) per block.
// ---------------------------------------------------------------------------
__global__ __launch_bounds__(256) void k1_partial(const float* __restrict__ x,
                                                  const float* __restrict__ W) {
    __shared__ float Ws[KT][NO + 1];   // [32][129] — pad 1 breaks STS conflicts
    __shared__ float Xs[KT][ND];       // [32][64]

    const int b   = blockIdx.x;
    const int sp  = blockIdx.y;
    const int tid = threadIdx.x;
    const int kbase0 = sp * KCH;

    float acc[8][4];
#pragma unroll
    for (int i = 0; i < 8; i++)
#pragma unroll
        for (int c = 0; c < 4; c++) acc[i][c] = 0.f;

    const int o0 = (tid >> 4) * 8;     // 0..120 step 8
    const int d0 = (tid & 15) * 4;     // 0..60  step 4

    for (int kt = 0; kt < KCH; kt += KT) {
        const int kbase = kbase0 + kt;
        // Load W tile: 32 x 128. Consecutive tid -> consecutive kk within one o:
        // global reads coalesced 128B; STS to [kk][o] with pad-129 -> no conflicts.
#pragma unroll
        for (int j = 0; j < 16; j++) {
            int idx = tid + j * 256;
            int o = idx >> 5, kk = idx & 31;
            Ws[kk][o] = W[o * NS + kbase + kk];
        }
        // Load X tile: 32 x 64, fully coalesced.
#pragma unroll
        for (int j = 0; j < 8; j++) {
            int idx = tid + j * 256;
            int kk = idx >> 6, d = idx & 63;
            Xs[kk][d] = x[(size_t)b * NS * ND + (size_t)(kbase + kk) * ND + d];
        }
        __syncthreads();

#pragma unroll
        for (int k = 0; k < KT; k++) {
            float4 xv = *(const float4*)&Xs[k][d0];
#pragma unroll
            for (int i = 0; i < 8; i++) {
                float w = Ws[k][o0 + i];   // 16-thread broadcast, conflict-free
                acc[i][0] += w * xv.x;
                acc[i][1] += w * xv.y;
                acc[i][2] += w * xv.z;
                acc[i][3] += w * xv.w;
            }
        }
        __syncthreads();
    }

    float* dst = &g_Ypart[((size_t)(sp * NB + b) * NO) * ND];
#pragma unroll
    for (int i = 0; i < 8; i++) {
        *(float4*)&dst[(o0 + i) * ND + d0] =
            make_float4(acc[i][0], acc[i][1], acc[i][2], acc[i][3]);
    }
}

// ---------------------------------------------------------------------------
// Kernel 1b: reduce the SPLIT partials.  Y[e] = sum_p Ypart[p][e]
// float4-vectorized: NB*NO*ND/4 = 32768 float4 elements.
// ---------------------------------------------------------------------------
__global__ __launch_bounds__(256) void k1_reduce() {
    int e = blockIdx.x * 256 + threadIdx.x;   // float4 index
    const float4* src = (const float4*)g_Ypart;
    const int stride = NB * NO * ND / 4;      // 32768
    float4 s = src[e];
#pragma unroll
    for (int p = 1; p < SPLIT; p++) {
        float4 v = src[(size_t)p * stride + e];
        s.x += v.x; s.y += v.y; s.z += v.z; s.w += v.w;
    }
    ((float4*)g_Y)[e] = s;
}

// ---------------------------------------------------------------------------
// Kernel 2: per-batch  out[s, o] = sum_d x[b,s,d] * Y[b,o,d] + bias[o]
// grid (16 s-tiles, NB), 256 threads, 128x128 output tile, K=64.
// Each thread: 8 s (stride 16) x 8 o (stride 16) accumulators.
// ---------------------------------------------------------------------------
__global__ __launch_bounds__(256) void k2(const float* __restrict__ x,
                                          const float* __restrict__ bias,
                                          float* __restrict__ out) {
    extern __shared__ float sm[];
    float* Xs = sm;                 // [128][PAD]
    float* Ys = sm + 128 * PAD;     // [128][PAD]

    const int st  = blockIdx.x;
    const int b   = blockIdx.y;
    const int tid = threadIdx.x;
    const int s0  = st * 128;

    // Load X tile [128 s][64 d] (2048 float4, 8 per thread, coalesced)
    const float4* xg = (const float4*)&x[((size_t)b * NS + s0) * ND];
#pragma unroll
    for (int j = 0; j < 8; j++) {
        int idx = tid + j * 256;
        int s = idx >> 4, d4 = idx & 15;
        *(float4*)&Xs[s * PAD + d4 * 4] = xg[idx];
    }
    // Load Y tile [128 o][64 d]
    const float4* yg = (const float4*)&g_Y[(size_t)b * NO * ND];
#pragma unroll
    for (int j = 0; j < 8; j++) {
        int idx = tid + j * 256;
        int o = idx >> 4, d4 = idx & 15;
        *(float4*)&Ys[o * PAD + d4 * 4] = yg[idx];
    }
    __syncthreads();

    const int sg = tid >> 4;   // 0..15 — rows sg + 16*i (warp-consecutive)
    const int og = tid & 15;   // 0..15 — rows og + 16*j (warp-consecutive)

    float acc[8][8];
#pragma unroll
    for (int i = 0; i < 8; i++)
#pragma unroll
        for (int j = 0; j < 8; j++) acc[i][j] = 0.f;

#pragma unroll
    for (int d = 0; d < ND; d += 4) {
        float4 xv[8];
#pragma unroll
        for (int i = 0; i < 8; i++)
            xv[i] = *(const float4*)&Xs[(sg + 16 * i) * PAD + d];
#pragma unroll
        for (int j = 0; j < 8; j++) {
            float4 yv = *(const float4*)&Ys[(og + 16 * j) * PAD + d];
#pragma unroll
            for (int i = 0; i < 8; i++) {
                acc[i][j] += xv[i].x * yv.x;
                acc[i][j] += xv[i].y * yv.y;
                acc[i][j] += xv[i].z * yv.z;
                acc[i][j] += xv[i].w * yv.w;
            }
        }
    }

    // Epilogue: +bias, write out
#pragma unroll
    for (int j = 0; j < 8; j++) {
        int o = og + 16 * j;
        float bb = bias[o];
#pragma unroll
        for (int i = 0; i < 8; i++) {
            int s = s0 + sg + 16 * i;
            out[((size_t)b * NS + s) * NO + o] = acc[i][j] + bb;
        }
    }
}

// ---------------------------------------------------------------------------
extern "C" void kernel_launch(void* const* d_in, const int* in_sizes, int n_in,
                              void* d_out, int out_size) {
    // Identify inputs by element count (robust to ordering):
    //   x: 16*2048*64 = 2097152, W: 128*2048 = 262144, bias: 128
    const float* x = nullptr;
    const float* W = nullptr;
    const float* bias = nullptr;
    for (int i = 0; i < n_in; i++) {
        if (in_sizes[i] == NB * NS * ND)      x = (const float*)d_in[i];
        else if (in_sizes[i] == NO * NS)      W = (const float*)d_in[i];
        else if (in_sizes[i] == NO)           bias = (const float*)d_in[i];
    }
    float* out = (float*)d_out;

    const int smem2 = 2 * 128 * PAD * sizeof(float);  // 69632 B > 48K -> opt-in
    cudaFuncSetAttribute(k2, cudaFuncAttributeMaxDynamicSharedMemorySize, smem2);

    k1_partial<<<dim3(NB, SPLIT), 256>>>(x, W);
    k1_reduce<<<(NB * NO * ND / 4) / 256, 256>>>();
    k2<<<dim3(NS / 128, NB), 256, smem2>>>(x, bias, out);
}